// round 11
// baseline (speedup 1.0000x reference)
#include <cuda_runtime.h>
#include <cstdint>

#define PB 4
#define PN 16384
#define PS 2048
#define PC 64
#define PK 33
#define PNS 32
#define JTOT (PS * PK)        // 67584
#define OUTC (6 + PC)         // 70
#define GR 10
#define NC (GR * GR * GR)     // 1000
#define CAP 256
#define TJ 128
#define NB2 256               // fused build+ball blocks (co-resident: 2/SM)

__device__ int    g_idx[PB * PS * PK];
__device__ float4 g_featT4[(size_t)PB * PN * PC / 4];
__device__ int    g_cellStart[PB * (NC + 1)];
__device__ int    g_cellCnt[PB * NC];    // zero-init; re-zeroed each run
__device__ int    g_cursor[PB * NC];
__device__ float4 g_pts[PB * PN];        // grid-reordered {x,y,z,bitcast(idx)}
__device__ unsigned g_bar_cnt;           // returns to 0 after each barrier
__device__ unsigned g_bar_gen;           // monotone; compared relatively

__device__ __forceinline__ int cell_of(float x, float y, float z) {
    int ix = min((int)(x * 10.0f), GR - 1);
    int iy = min((int)(y * 10.0f), GR - 1);
    int iz = min((int)(z * 10.0f), GR - 1);
    return (iz * GR + iy) * GR + ix;
}

__device__ __forceinline__ void grid_barrier() {
    __syncthreads();
    if (threadIdx.x == 0) {
        __threadfence();
        volatile unsigned* vgen = &g_bar_gen;
        unsigned gen = *vgen;
        if (atomicAdd(&g_bar_cnt, 1u) == NB2 - 1) {
            g_bar_cnt = 0;
            __threadfence();
            atomicAdd(&g_bar_gen, 1u);
        } else {
            while (*vgen == gen) __nanosleep(32);
        }
        __threadfence();
    }
    __syncthreads();
}

// ---------------------------------------------------------------------------
// Fused: count -> scan -> scatter -> ball query. 256 blocks, 3 barriers.
// ---------------------------------------------------------------------------
__global__ void __launch_bounds__(256, 2) build_and_ball(
    const float* __restrict__ xyz, const float* __restrict__ new_xyz,
    const int* __restrict__ fps)
{
    __shared__ int buf[8][264];
    __shared__ int scum[8][10];
    __shared__ int sadj[8][10];
    __shared__ int ssc[256];        // scan scratch

    int blk = blockIdx.x;
    int t   = threadIdx.x;
    int gi  = blk * 256 + t;        // 0..65535 = one point per thread
    int b_pt = gi >> 14;
    int n_pt = gi & (PN - 1);

    // ---- Phase A: count (global atomics -> L2) ----
    {
        const float* p = xyz + 3 * (size_t)gi;
        atomicAdd(&g_cellCnt[b_pt * NC + cell_of(p[0], p[1], p[2])], 1);
    }
    grid_barrier();

    // ---- Phase B: scan (blocks 0..3, one batch each) ----
    if (blk < PB) {
        int b  = blk;
        int c0 = t * 4;
        int v0 = 0, v1 = 0, v2 = 0, v3 = 0;
        if (c0 < NC)     v0 = g_cellCnt[b * NC + c0];
        if (c0 + 1 < NC) v1 = g_cellCnt[b * NC + c0 + 1];
        if (c0 + 2 < NC) v2 = g_cellCnt[b * NC + c0 + 2];
        if (c0 + 3 < NC) v3 = g_cellCnt[b * NC + c0 + 3];
        int tsum = v0 + v1 + v2 + v3;
        ssc[t] = tsum;
        __syncthreads();
#pragma unroll
        for (int off = 1; off < 256; off <<= 1) {
            int v = (t >= off) ? ssc[t - off] : 0;
            __syncthreads();
            if (t >= off) ssc[t] += v;
            __syncthreads();
        }
        int run = ssc[t] - tsum;                 // exclusive prefix
        if (t == 255) g_cellStart[b * (NC + 1) + NC] = ssc[255];
        int c = c0;
        int vals[4] = {v0, v1, v2, v3};
#pragma unroll
        for (int j = 0; j < 4; j++, c++) {
            if (c < NC) {
                g_cellStart[b * (NC + 1) + c] = run;
                g_cursor[b * NC + c]          = run;
                g_cellCnt[b * NC + c]         = 0;   // reset for next replay
                run += vals[j];
            }
        }
    }
    grid_barrier();

    // ---- Phase C: scatter (xyz re-read is L2-hot; cursor atomics -> L2) ----
    {
        const float* p = xyz + 3 * (size_t)gi;
        float x = p[0], y = p[1], z = p[2];
        int pos = atomicAdd(&g_cursor[b_pt * NC + cell_of(x, y, z)], 1);
        g_pts[(size_t)b_pt * PN + pos] = make_float4(x, y, z, __int_as_float(n_pt));
    }
    grid_barrier();

    // ---- Phase D: ball query, 4 queries per warp (no barrier after) ----
    int wi   = t >> 5;
    int lane = t & 31;
    int* wbuf = buf[wi];
    int* cum  = scum[wi];
    int* adj  = sadj[wi];
    const float R2 = 0.01f;          // (float)(0.1*0.1 in f64) == 0.01f
    const unsigned FULL = 0xffffffffu;

    for (int gw = blk * 8 + wi; gw < PB * PS; gw += NB2 * 8) {
        int b = gw >> 11;
        int s = gw & (PS - 1);
        const float* q = new_xyz + ((size_t)b * PS + s) * 3;
        float qx = q[0], qy = q[1], qz = q[2];
        int* out = g_idx + ((size_t)b * PS + s) * PK;
        if (lane == 0) out[0] = fps[b * PS + s];

        int cx = min((int)(qx * 10.0f), GR - 1);
        int cy = min((int)(qy * 10.0f), GR - 1);
        int cz = min((int)(qz * 10.0f), GR - 1);
        const float4* pts = g_pts + (size_t)b * PN;
        const int*    cst = g_cellStart + (size_t)b * (NC + 1);

        int z0 = max(cz - 1, 0), z1 = min(cz + 1, GR - 1);
        int y0 = max(cy - 1, 0), y1 = min(cy + 1, GR - 1);
        int x0 = max(cx - 1, 0), x1 = min(cx + 1, GR - 1);

        int nseg = 0, T = 0;
        for (int zz = z0; zz <= z1; zz++) {
            for (int yy = y0; yy <= y1; yy++) {
                int cbase = (zz * GR + yy) * GR;
                int beg = cst[cbase + x0];
                int end = cst[cbase + x1 + 1];
                int len = end - beg;
                if (len > 0) {
                    if (lane == 0) { adj[nseg] = beg - T; cum[nseg] = T + len; }
                    nseg++;
                    T += len;
                }
            }
        }
        __syncwarp();

        int cnt = 0;
        int seg = 0;
        for (int base = 0; base < T; base += 32) {
            int idx = base + lane;
            bool hit = false;
            int pid = 0;
            if (idx < T) {
                while (idx >= cum[seg]) seg++;
                float4 v = pts[adj[seg] + idx];
                float dx = __fsub_rn(qx, v.x);
                float dy = __fsub_rn(qy, v.y);
                float dz = __fsub_rn(qz, v.z);
                float d2 = __fadd_rn(__fadd_rn(__fmul_rn(dx, dx), __fmul_rn(dy, dy)),
                                     __fmul_rn(dz, dz));
                hit = d2 < R2;
                pid = __float_as_int(v.w);
            }
            unsigned m = __ballot_sync(FULL, hit);
            if (hit) {
                int pos = cnt + __popc(m & ((1u << lane) - 1u));
                if (pos < CAP) wbuf[pos] = pid;
            }
            cnt += __popc(m);
        }

        int M  = min(cnt, CAP);
        int Mp = (M + 3) & ~3;
        if (lane < Mp - M) wbuf[M + lane] = 0x7fffffff;
        __syncwarp();

        int minhit = 0x7fffffff;
        const int4* b4 = (const int4*)wbuf;
        for (int i = lane; i < M; i += 32) {
            int h = wbuf[i];
            minhit = min(minhit, h);
            int rank = 0;
            int nq = Mp >> 2;
            for (int j = 0; j < nq; j++) {
                int4 w = b4[j];
                rank += (w.x < h) + (w.y < h) + (w.z < h) + (w.w < h);
            }
            if (rank < PNS) out[1 + rank] = h;
        }
#pragma unroll
        for (int off = 16; off; off >>= 1)
            minhit = min(minhit, __shfl_xor_sync(FULL, minhit, off));
        int fill = (cnt == 0) ? 0 : minhit;
        int c = min(cnt, PNS);
        if (lane >= c) out[1 + lane] = fill;
        __syncwarp();
        seg = 0;
    }
}

// ---------------------------------------------------------------------------
// Transpose features (B, C, N) -> (B, N, C). 64x64 tiles, float4 both ways.
// ---------------------------------------------------------------------------
__global__ void __launch_bounds__(256) transpose_feat(const float* __restrict__ f) {
    __shared__ float tile[64][65];
    int b  = blockIdx.y;
    int n0 = blockIdx.x * 64;
    const float* fb = f + (size_t)b * PC * PN;
    float4*     ftb = g_featT4 + (size_t)b * PN * (PC / 4);
    int t  = threadIdx.x;
    int qd = t & 15;
    int r0 = t >> 4;
#pragma unroll
    for (int k = 0; k < 4; k++) {
        int c = r0 + k * 16;
        float4 v = *(const float4*)(fb + (size_t)c * PN + n0 + qd * 4);
        tile[c][qd * 4 + 0] = v.x;
        tile[c][qd * 4 + 1] = v.y;
        tile[c][qd * 4 + 2] = v.z;
        tile[c][qd * 4 + 3] = v.w;
    }
    __syncthreads();
#pragma unroll
    for (int k = 0; k < 4; k++) {
        int n = r0 + k * 16;
        float4 v;
        v.x = tile[qd * 4 + 0][n];
        v.y = tile[qd * 4 + 1][n];
        v.z = tile[qd * 4 + 2][n];
        v.w = tile[qd * 4 + 3][n];
        ftb[(size_t)(n0 + n) * (PC / 4) + qd] = v;
    }
}

// ---------------------------------------------------------------------------
// Gather + write (R8 version: coalesced 256B row reads, scalar stcs writes)
// ---------------------------------------------------------------------------
__global__ void __launch_bounds__(256) gather_write(const float* __restrict__ xyz,
                                                    const float* __restrict__ new_xyz,
                                                    float* __restrict__ out) {
    __shared__ float tile[TJ][PC + 1];
    __shared__ int   sn[TJ];
    __shared__ float sxyz[TJ][3];
    __shared__ float sq[TJ][3];

    int bj  = blockIdx.x;
    int b   = bj / (JTOT / TJ);
    int j0  = (bj - b * (JTOT / TJ)) * TJ;
    int tid = threadIdx.x;

    if (tid < TJ) {
        int j = j0 + tid;
        int n = g_idx[(size_t)b * JTOT + j];
        sn[tid] = n;
        const float* p = xyz + ((size_t)b * PN + n) * 3;
        sxyz[tid][0] = p[0];  sxyz[tid][1] = p[1];  sxyz[tid][2] = p[2];
    } else {
        int jt = tid - TJ;
        int s  = (j0 + jt) / PK;
        const float* qp = new_xyz + ((size_t)b * PS + s) * 3;
        sq[jt][0] = qp[0];  sq[jt][1] = qp[1];  sq[jt][2] = qp[2];
    }
    __syncthreads();

    const float4* ftb = g_featT4 + (size_t)b * PN * (PC / 4);
#pragma unroll
    for (int it = 0; it < 8; it++) {
        int lin = tid + it * 256;
        int jj  = lin >> 4;
        int qd  = lin & 15;
        float4 v = ftb[(size_t)sn[jj] * (PC / 4) + qd];
        tile[jj][qd * 4 + 0] = v.x;
        tile[jj][qd * 4 + 1] = v.y;
        tile[jj][qd * 4 + 2] = v.z;
        tile[jj][qd * 4 + 3] = v.w;
    }
    __syncthreads();

    float* ob = out + (size_t)b * OUTC * JTOT + j0;
#pragma unroll
    for (int it = 0; it < 3; it++) {
        int idx  = it * 256 + tid;
        int c    = idx >> 7;
        int jpos = idx & (TJ - 1);
        float v = (c < 3) ? sxyz[jpos][c] : (sxyz[jpos][c - 3] - sq[jpos][c - 3]);
        __stcs(&ob[(size_t)c * JTOT + jpos], v);
    }
#pragma unroll
    for (int it = 0; it < 32; it++) {
        int idx  = it * 256 + tid;
        int c    = idx >> 7;
        int jpos = idx & (TJ - 1);
        __stcs(&ob[(size_t)(6 + c) * JTOT + jpos], tile[jpos][c]);
    }
}

// ---------------------------------------------------------------------------
extern "C" void kernel_launch(void* const* d_in, const int* in_sizes, int n_in,
                              void* d_out, int out_size) {
    const float* xyz      = (const float*)d_in[0];
    const float* new_xyz  = (const float*)d_in[1];
    const float* features = (const float*)d_in[2];
    const int*   fps_idx  = (const int*)  d_in[3];
    float* out = (float*)d_out;

    static cudaStream_t sT = nullptr;
    static cudaEvent_t evFork = nullptr, evT = nullptr;
    if (!sT) {
        cudaStreamCreateWithFlags(&sT, cudaStreamNonBlocking);
        cudaEventCreateWithFlags(&evFork, cudaEventDisableTiming);
        cudaEventCreateWithFlags(&evT, cudaEventDisableTiming);
    }

    // Fork: transpose concurrent with fused build+ball
    cudaEventRecord(evFork, 0);
    cudaStreamWaitEvent(sT, evFork, 0);
    {
        dim3 grid(PN / 64, PB);
        transpose_feat<<<grid, 256, 0, sT>>>(features);
    }
    cudaEventRecord(evT, sT);

    // Fused grid build + ball query (one launch, 3 internal barriers)
    build_and_ball<<<NB2, 256>>>(xyz, new_xyz, fps_idx);

    // Join, then gather + write
    cudaStreamWaitEvent(0, evT, 0);
    gather_write<<<PB * (JTOT / TJ), 256>>>(xyz, new_xyz, out);
}

// round 12
// speedup vs baseline: 1.3162x; 1.3162x over previous
#include <cuda_runtime.h>
#include <cstdint>

#define PB 4
#define PN 16384
#define PS 2048
#define PC 64
#define PK 33
#define PNS 32
#define JTOT (PS * PK)        // 67584
#define OUTC (6 + PC)         // 70
#define GR 10
#define NC (GR * GR * GR)     // 1000
#define CAP 256
#define TJ 128

__device__ int    g_idx[PB * PS * PK];
__device__ float4 g_featT4[(size_t)PB * PN * PC / 4];
__device__ int    g_cellStart[PB * (NC + 1)];
__device__ int    g_cellCnt[PB * NC];    // zero-init; scan re-zeroes after read
__device__ int    g_cursor[PB * NC];
__device__ float4 g_pts[PB * PN];        // grid-reordered {x,y,z,bitcast(idx)}

__device__ __forceinline__ int cell_of(float x, float y, float z) {
    int ix = min((int)(x * 10.0f), GR - 1);
    int iy = min((int)(y * 10.0f), GR - 1);
    int iz = min((int)(z * 10.0f), GR - 1);
    return (iz * GR + iy) * GR + ix;
}

// ---------------------------------------------------------------------------
// Grid build: global-atomic count -> per-batch scan -> global-cursor scatter
// ---------------------------------------------------------------------------
__global__ void __launch_bounds__(256) count_cells(const float* __restrict__ xyz) {
    int i = blockIdx.x * 256 + threadIdx.x;          // 0..65535
    const float* p = xyz + 3 * (size_t)i;
    int b = i >> 14;
    atomicAdd(&g_cellCnt[b * NC + cell_of(p[0], p[1], p[2])], 1);
}

__global__ void __launch_bounds__(1024) scan_cells() {
    __shared__ int s[1024];
    int b = blockIdx.x;
    int t = threadIdx.x;
    int cnt = (t < NC) ? g_cellCnt[b * NC + t] : 0;
    s[t] = cnt;
    __syncthreads();
#pragma unroll
    for (int off = 1; off < 1024; off <<= 1) {
        int v = (t >= off) ? s[t - off] : 0;
        __syncthreads();
        if (t >= off) s[t] += v;
        __syncthreads();
    }
    if (t < NC) {
        int excl = s[t] - cnt;
        g_cellStart[b * (NC + 1) + t] = excl;
        g_cursor[b * NC + t] = excl;
        g_cellCnt[b * NC + t] = 0;                  // reset for next replay
        if (t == NC - 1) g_cellStart[b * (NC + 1) + NC] = s[t];
    }
}

__global__ void __launch_bounds__(256) scatter_pts(const float* __restrict__ xyz) {
    int i = blockIdx.x * 256 + threadIdx.x;
    const float* p = xyz + 3 * (size_t)i;
    float x = p[0], y = p[1], z = p[2];
    int b = i >> 14;
    int n = i & (PN - 1);
    int pos = atomicAdd(&g_cursor[b * NC + cell_of(x, y, z)], 1);
    g_pts[(size_t)b * PN + pos] = make_float4(x, y, z, __int_as_float(n));
}

// ---------------------------------------------------------------------------
// Ball query — one warp per query; dense candidate packing over the up-to-9
// contiguous cell-row segments; rank-select 32 smallest hit indices.
// ---------------------------------------------------------------------------
__global__ void __launch_bounds__(256) ball_query_grid(const float* __restrict__ new_xyz,
                                                       const int*   __restrict__ fps) {
    __shared__ int buf[8][264];
    __shared__ int scum[8][10];
    __shared__ int sadj[8][10];
    int wi   = threadIdx.x >> 5;
    int lane = threadIdx.x & 31;
    int gw   = blockIdx.x * 8 + wi;
    int b = gw >> 11;
    int s = gw & (PS - 1);

    const float* q = new_xyz + ((size_t)b * PS + s) * 3;
    float qx = q[0], qy = q[1], qz = q[2];
    int* out = g_idx + ((size_t)b * PS + s) * PK;
    if (lane == 0) out[0] = fps[b * PS + s];

    int cx = min((int)(qx * 10.0f), GR - 1);
    int cy = min((int)(qy * 10.0f), GR - 1);
    int cz = min((int)(qz * 10.0f), GR - 1);

    const float4* pts = g_pts + (size_t)b * PN;
    const int*    cst = g_cellStart + (size_t)b * (NC + 1);
    int* wbuf = buf[wi];
    int* cum  = scum[wi];
    int* adj  = sadj[wi];

    int z0 = max(cz - 1, 0), z1 = min(cz + 1, GR - 1);
    int y0 = max(cy - 1, 0), y1 = min(cy + 1, GR - 1);
    int x0 = max(cx - 1, 0), x1 = min(cx + 1, GR - 1);

    int nseg = 0, T = 0;
    for (int zz = z0; zz <= z1; zz++) {
        for (int yy = y0; yy <= y1; yy++) {
            int cbase = (zz * GR + yy) * GR;
            int beg = cst[cbase + x0];
            int end = cst[cbase + x1 + 1];
            int len = end - beg;
            if (len > 0) {
                if (lane == 0) { adj[nseg] = beg - T; cum[nseg] = T + len; }
                nseg++;
                T += len;
            }
        }
    }
    __syncwarp();

    const float R2 = 0.01f;   // (float)(0.1*0.1 in f64) == 0.01f
    const unsigned FULL = 0xffffffffu;
    int cnt = 0;
    int seg = 0;

    for (int base = 0; base < T; base += 32) {
        int idx = base + lane;
        bool hit = false;
        int pid = 0;
        if (idx < T) {
            while (idx >= cum[seg]) seg++;
            float4 v = pts[adj[seg] + idx];
            float dx = __fsub_rn(qx, v.x);
            float dy = __fsub_rn(qy, v.y);
            float dz = __fsub_rn(qz, v.z);
            float d2 = __fadd_rn(__fadd_rn(__fmul_rn(dx, dx), __fmul_rn(dy, dy)),
                                 __fmul_rn(dz, dz));
            hit = d2 < R2;
            pid = __float_as_int(v.w);
        }
        unsigned m = __ballot_sync(FULL, hit);
        if (hit) {
            int pos = cnt + __popc(m & ((1u << lane) - 1u));
            if (pos < CAP) wbuf[pos] = pid;
        }
        cnt += __popc(m);
    }

    int M  = min(cnt, CAP);
    int Mp = (M + 3) & ~3;
    if (lane < Mp - M) wbuf[M + lane] = 0x7fffffff;
    __syncwarp();

    int minhit = 0x7fffffff;
    const int4* b4 = (const int4*)wbuf;
    for (int i = lane; i < M; i += 32) {
        int h = wbuf[i];
        minhit = min(minhit, h);
        int rank = 0;
        int nq = Mp >> 2;
        for (int j = 0; j < nq; j++) {
            int4 w = b4[j];
            rank += (w.x < h) + (w.y < h) + (w.z < h) + (w.w < h);
        }
        if (rank < PNS) out[1 + rank] = h;
    }
#pragma unroll
    for (int off = 16; off; off >>= 1)
        minhit = min(minhit, __shfl_xor_sync(FULL, minhit, off));
    int fill = (cnt == 0) ? 0 : minhit;
    int c = min(cnt, PNS);
    if (lane >= c) out[1 + lane] = fill;
}

// ---------------------------------------------------------------------------
// Transpose features (B, C, N) -> (B, N, C). 64x64 tiles, float4 both ways.
// ---------------------------------------------------------------------------
__global__ void __launch_bounds__(256) transpose_feat(const float* __restrict__ f) {
    __shared__ float tile[64][65];
    int b  = blockIdx.y;
    int n0 = blockIdx.x * 64;
    const float* fb = f + (size_t)b * PC * PN;
    float4*     ftb = g_featT4 + (size_t)b * PN * (PC / 4);
    int t  = threadIdx.x;
    int qd = t & 15;
    int r0 = t >> 4;
#pragma unroll
    for (int k = 0; k < 4; k++) {
        int c = r0 + k * 16;
        float4 v = *(const float4*)(fb + (size_t)c * PN + n0 + qd * 4);
        tile[c][qd * 4 + 0] = v.x;
        tile[c][qd * 4 + 1] = v.y;
        tile[c][qd * 4 + 2] = v.z;
        tile[c][qd * 4 + 3] = v.w;
    }
    __syncthreads();
#pragma unroll
    for (int k = 0; k < 4; k++) {
        int n = r0 + k * 16;
        float4 v;
        v.x = tile[qd * 4 + 0][n];
        v.y = tile[qd * 4 + 1][n];
        v.z = tile[qd * 4 + 2][n];
        v.w = tile[qd * 4 + 3][n];
        ftb[(size_t)(n0 + n) * (PC / 4) + qd] = v;
    }
}

// ---------------------------------------------------------------------------
// Gather + write (exact R8 version: coalesced 256B row reads, stcs writes)
// ---------------------------------------------------------------------------
__global__ void __launch_bounds__(256) gather_write(const float* __restrict__ xyz,
                                                    const float* __restrict__ new_xyz,
                                                    float* __restrict__ out) {
    __shared__ float tile[TJ][PC + 1];
    __shared__ int   sn[TJ];
    __shared__ float sxyz[TJ][3];
    __shared__ float sq[TJ][3];

    int bj  = blockIdx.x;
    int b   = bj / (JTOT / TJ);
    int j0  = (bj - b * (JTOT / TJ)) * TJ;
    int tid = threadIdx.x;

    if (tid < TJ) {
        int j = j0 + tid;
        int n = g_idx[(size_t)b * JTOT + j];
        sn[tid] = n;
        const float* p = xyz + ((size_t)b * PN + n) * 3;
        sxyz[tid][0] = p[0];  sxyz[tid][1] = p[1];  sxyz[tid][2] = p[2];
    } else {
        int jt = tid - TJ;
        int s  = (j0 + jt) / PK;
        const float* qp = new_xyz + ((size_t)b * PS + s) * 3;
        sq[jt][0] = qp[0];  sq[jt][1] = qp[1];  sq[jt][2] = qp[2];
    }
    __syncthreads();

    const float4* ftb = g_featT4 + (size_t)b * PN * (PC / 4);
#pragma unroll
    for (int it = 0; it < 8; it++) {
        int lin = tid + it * 256;
        int jj  = lin >> 4;
        int qd  = lin & 15;
        float4 v = ftb[(size_t)sn[jj] * (PC / 4) + qd];
        tile[jj][qd * 4 + 0] = v.x;
        tile[jj][qd * 4 + 1] = v.y;
        tile[jj][qd * 4 + 2] = v.z;
        tile[jj][qd * 4 + 3] = v.w;
    }
    __syncthreads();

    float* ob = out + (size_t)b * OUTC * JTOT + j0;
#pragma unroll
    for (int it = 0; it < 3; it++) {
        int idx  = it * 256 + tid;
        int c    = idx >> 7;
        int jpos = idx & (TJ - 1);
        float v = (c < 3) ? sxyz[jpos][c] : (sxyz[jpos][c - 3] - sq[jpos][c - 3]);
        __stcs(&ob[(size_t)c * JTOT + jpos], v);
    }
#pragma unroll
    for (int it = 0; it < 32; it++) {
        int idx  = it * 256 + tid;
        int c    = idx >> 7;
        int jpos = idx & (TJ - 1);
        __stcs(&ob[(size_t)(6 + c) * JTOT + jpos], tile[jpos][c]);
    }
}

// ---------------------------------------------------------------------------
extern "C" void kernel_launch(void* const* d_in, const int* in_sizes, int n_in,
                              void* d_out, int out_size) {
    const float* xyz      = (const float*)d_in[0];
    const float* new_xyz  = (const float*)d_in[1];
    const float* features = (const float*)d_in[2];
    const int*   fps_idx  = (const int*)  d_in[3];
    float* out = (float*)d_out;

    static cudaStream_t sT = nullptr;
    static cudaEvent_t evFork = nullptr, evT = nullptr;
    if (!sT) {
        cudaStreamCreateWithFlags(&sT, cudaStreamNonBlocking);
        cudaEventCreateWithFlags(&evFork, cudaEventDisableTiming);
        cudaEventCreateWithFlags(&evT, cudaEventDisableTiming);
    }

    // Fork: transpose concurrent with grid build + ball query
    cudaEventRecord(evFork, 0);
    cudaStreamWaitEvent(sT, evFork, 0);
    {
        dim3 grid(PN / 64, PB);
        transpose_feat<<<grid, 256, 0, sT>>>(features);
    }
    cudaEventRecord(evT, sT);

    // Grid build
    count_cells<<<PB * PN / 256, 256>>>(xyz);
    scan_cells<<<PB, 1024>>>();
    scatter_pts<<<PB * PN / 256, 256>>>(xyz);

    // Ball query
    ball_query_grid<<<PB * PS / 8, 256>>>(new_xyz, fps_idx);

    // Join, then gather + write
    cudaStreamWaitEvent(0, evT, 0);
    gather_write<<<PB * (JTOT / TJ), 256>>>(xyz, new_xyz, out);
}

// round 13
// speedup vs baseline: 1.3812x; 1.0494x over previous
#include <cuda_runtime.h>
#include <cstdint>

#define PB 4
#define PN 16384
#define PS 2048
#define PC 64
#define PK 33
#define PNS 32
#define JTOT (PS * PK)        // 67584
#define OUTC (6 + PC)         // 70
#define GR 10
#define NC (GR * GR * GR)     // 1000
#define CAP 256
#define TJ 128
#define BCAP 96               // per-cell bucket capacity (Poisson(16.4); P(>96)~1e-18)

__device__ int    g_idx[PB * PS * PK];
__device__ float4 g_featT4[(size_t)PB * PN * PC / 4];
__device__ int    g_cellCnt[PB * NC];                 // zero-init; gather tail re-zeroes
__device__ float4 g_ptsB[(size_t)PB * NC * BCAP];     // padded per-cell buckets

__device__ __forceinline__ int cell_of(float x, float y, float z) {
    int ix = min((int)(x * 10.0f), GR - 1);
    int iy = min((int)(y * 10.0f), GR - 1);
    int iz = min((int)(z * 10.0f), GR - 1);
    return (iz * GR + iy) * GR + ix;
}

// ---------------------------------------------------------------------------
// Grid build: ONE pass. Direct scatter into padded buckets via atomic cursors.
// ---------------------------------------------------------------------------
__global__ void __launch_bounds__(256) scatter_direct(const float* __restrict__ xyz) {
    int i = blockIdx.x * 256 + threadIdx.x;           // 0..65535
    const float* p = xyz + 3 * (size_t)i;
    float x = p[0], y = p[1], z = p[2];
    int b = i >> 14;
    int n = i & (PN - 1);
    int cell = b * NC + cell_of(x, y, z);
    int pos = atomicAdd(&g_cellCnt[cell], 1);
    if (pos < BCAP)
        g_ptsB[(size_t)cell * BCAP + pos] = make_float4(x, y, z, __int_as_float(n));
}

// ---------------------------------------------------------------------------
// Ball query — one warp per query; dense candidate packing over up to 27
// per-cell bucket segments; rank-select 32 smallest hit indices.
// ---------------------------------------------------------------------------
__global__ void __launch_bounds__(256) ball_query_grid(const float* __restrict__ new_xyz,
                                                       const int*   __restrict__ fps) {
    __shared__ int buf[8][264];
    __shared__ int scum[8][27];
    __shared__ int sadj[8][27];
    int wi   = threadIdx.x >> 5;
    int lane = threadIdx.x & 31;
    int gw   = blockIdx.x * 8 + wi;
    int b = gw >> 11;
    int s = gw & (PS - 1);

    const float* q = new_xyz + ((size_t)b * PS + s) * 3;
    float qx = q[0], qy = q[1], qz = q[2];
    int* out = g_idx + ((size_t)b * PS + s) * PK;
    if (lane == 0) out[0] = fps[b * PS + s];

    int cx = min((int)(qx * 10.0f), GR - 1);
    int cy = min((int)(qy * 10.0f), GR - 1);
    int cz = min((int)(qz * 10.0f), GR - 1);

    const float4* pts = g_ptsB;       // global bucket array (batch offset in cell id)
    const int* cnt_arr = g_cellCnt;
    int* wbuf = buf[wi];
    int* cum  = scum[wi];
    int* adj  = sadj[wi];

    int z0 = max(cz - 1, 0), z1 = min(cz + 1, GR - 1);
    int y0 = max(cy - 1, 0), y1 = min(cy + 1, GR - 1);
    int x0 = max(cx - 1, 0), x1 = min(cx + 1, GR - 1);

    // Build flattened segment table over the (up to 27) neighbor buckets.
    int nseg = 0, T = 0;
    for (int zz = z0; zz <= z1; zz++) {
        for (int yy = y0; yy <= y1; yy++) {
            int rowbase = b * NC + (zz * GR + yy) * GR;
            for (int xx = x0; xx <= x1; xx++) {
                int cell = rowbase + xx;
                int len  = min(cnt_arr[cell], BCAP);   // uniform (broadcast) load
                if (len > 0) {
                    if (lane == 0) {
                        adj[nseg] = cell * BCAP - T;
                        cum[nseg] = T + len;
                    }
                    nseg++;
                    T += len;
                }
            }
        }
    }
    __syncwarp();

    const float R2 = 0.01f;   // (float)(0.1*0.1 in f64) == 0.01f
    const unsigned FULL = 0xffffffffu;
    int cnt = 0;
    int seg = 0;              // per-lane monotone segment pointer

    for (int base = 0; base < T; base += 32) {
        int idx = base + lane;
        bool hit = false;
        int pid = 0;
        if (idx < T) {
            while (idx >= cum[seg]) seg++;
            float4 v = pts[(size_t)adj[seg] + idx];
            float dx = __fsub_rn(qx, v.x);
            float dy = __fsub_rn(qy, v.y);
            float dz = __fsub_rn(qz, v.z);
            float d2 = __fadd_rn(__fadd_rn(__fmul_rn(dx, dx), __fmul_rn(dy, dy)),
                                 __fmul_rn(dz, dz));
            hit = d2 < R2;
            pid = __float_as_int(v.w);
        }
        unsigned m = __ballot_sync(FULL, hit);
        if (hit) {
            int pos = cnt + __popc(m & ((1u << lane) - 1u));
            if (pos < CAP) wbuf[pos] = pid;
        }
        cnt += __popc(m);
    }

    int M  = min(cnt, CAP);
    int Mp = (M + 3) & ~3;
    if (lane < Mp - M) wbuf[M + lane] = 0x7fffffff;
    __syncwarp();

    int minhit = 0x7fffffff;
    const int4* b4 = (const int4*)wbuf;
    for (int i = lane; i < M; i += 32) {
        int h = wbuf[i];
        minhit = min(minhit, h);
        int rank = 0;
        int nq = Mp >> 2;
        for (int j = 0; j < nq; j++) {
            int4 w = b4[j];
            rank += (w.x < h) + (w.y < h) + (w.z < h) + (w.w < h);
        }
        if (rank < PNS) out[1 + rank] = h;
    }
#pragma unroll
    for (int off = 16; off; off >>= 1)
        minhit = min(minhit, __shfl_xor_sync(FULL, minhit, off));
    int fill = (cnt == 0) ? 0 : minhit;
    int c = min(cnt, PNS);
    if (lane >= c) out[1 + lane] = fill;
}

// ---------------------------------------------------------------------------
// Transpose features (B, C, N) -> (B, N, C). 64x64 tiles, float4 both ways.
// ---------------------------------------------------------------------------
__global__ void __launch_bounds__(256) transpose_feat(const float* __restrict__ f) {
    __shared__ float tile[64][65];
    int b  = blockIdx.y;
    int n0 = blockIdx.x * 64;
    const float* fb = f + (size_t)b * PC * PN;
    float4*     ftb = g_featT4 + (size_t)b * PN * (PC / 4);
    int t  = threadIdx.x;
    int qd = t & 15;
    int r0 = t >> 4;
#pragma unroll
    for (int k = 0; k < 4; k++) {
        int c = r0 + k * 16;
        float4 v = *(const float4*)(fb + (size_t)c * PN + n0 + qd * 4);
        tile[c][qd * 4 + 0] = v.x;
        tile[c][qd * 4 + 1] = v.y;
        tile[c][qd * 4 + 2] = v.z;
        tile[c][qd * 4 + 3] = v.w;
    }
    __syncthreads();
#pragma unroll
    for (int k = 0; k < 4; k++) {
        int n = r0 + k * 16;
        float4 v;
        v.x = tile[qd * 4 + 0][n];
        v.y = tile[qd * 4 + 1][n];
        v.z = tile[qd * 4 + 2][n];
        v.w = tile[qd * 4 + 3][n];
        ftb[(size_t)(n0 + n) * (PC / 4) + qd] = v;
    }
}

// ---------------------------------------------------------------------------
// Gather + write (R8 version) + tail: reset g_cellCnt for next replay.
// ---------------------------------------------------------------------------
__global__ void __launch_bounds__(256) gather_write(const float* __restrict__ xyz,
                                                    const float* __restrict__ new_xyz,
                                                    float* __restrict__ out) {
    __shared__ float tile[TJ][PC + 1];
    __shared__ int   sn[TJ];
    __shared__ float sxyz[TJ][3];
    __shared__ float sq[TJ][3];

    int bj  = blockIdx.x;
    int b   = bj / (JTOT / TJ);
    int j0  = (bj - b * (JTOT / TJ)) * TJ;
    int tid = threadIdx.x;

    if (tid < TJ) {
        int j = j0 + tid;
        int n = g_idx[(size_t)b * JTOT + j];
        sn[tid] = n;
        const float* p = xyz + ((size_t)b * PN + n) * 3;
        sxyz[tid][0] = p[0];  sxyz[tid][1] = p[1];  sxyz[tid][2] = p[2];
    } else {
        int jt = tid - TJ;
        int s  = (j0 + jt) / PK;
        const float* qp = new_xyz + ((size_t)b * PS + s) * 3;
        sq[jt][0] = qp[0];  sq[jt][1] = qp[1];  sq[jt][2] = qp[2];
    }
    __syncthreads();

    const float4* ftb = g_featT4 + (size_t)b * PN * (PC / 4);
#pragma unroll
    for (int it = 0; it < 8; it++) {
        int lin = tid + it * 256;
        int jj  = lin >> 4;
        int qd  = lin & 15;
        float4 v = ftb[(size_t)sn[jj] * (PC / 4) + qd];
        tile[jj][qd * 4 + 0] = v.x;
        tile[jj][qd * 4 + 1] = v.y;
        tile[jj][qd * 4 + 2] = v.z;
        tile[jj][qd * 4 + 3] = v.w;
    }
    __syncthreads();

    float* ob = out + (size_t)b * OUTC * JTOT + j0;
#pragma unroll
    for (int it = 0; it < 3; it++) {
        int idx  = it * 256 + tid;
        int c    = idx >> 7;
        int jpos = idx & (TJ - 1);
        float v = (c < 3) ? sxyz[jpos][c] : (sxyz[jpos][c - 3] - sq[jpos][c - 3]);
        __stcs(&ob[(size_t)c * JTOT + jpos], v);
    }
#pragma unroll
    for (int it = 0; it < 32; it++) {
        int idx  = it * 256 + tid;
        int c    = idx >> 7;
        int jpos = idx & (TJ - 1);
        __stcs(&ob[(size_t)(6 + c) * JTOT + jpos], tile[jpos][c]);
    }

    // Tail: reset cell counters for the next replay (runs strictly after
    // ball_query_grid's reads — same-stream kernel ordering).
    if (bj < 16) {
        int i = bj * 256 + tid;
        if (i < PB * NC) g_cellCnt[i] = 0;
    }
}

// ---------------------------------------------------------------------------
extern "C" void kernel_launch(void* const* d_in, const int* in_sizes, int n_in,
                              void* d_out, int out_size) {
    const float* xyz      = (const float*)d_in[0];
    const float* new_xyz  = (const float*)d_in[1];
    const float* features = (const float*)d_in[2];
    const int*   fps_idx  = (const int*)  d_in[3];
    float* out = (float*)d_out;

    static cudaStream_t sT = nullptr;
    static cudaEvent_t evFork = nullptr, evT = nullptr;
    if (!sT) {
        cudaStreamCreateWithFlags(&sT, cudaStreamNonBlocking);
        cudaEventCreateWithFlags(&evFork, cudaEventDisableTiming);
        cudaEventCreateWithFlags(&evT, cudaEventDisableTiming);
    }

    // Fork: transpose concurrent with grid build + ball query
    cudaEventRecord(evFork, 0);
    cudaStreamWaitEvent(sT, evFork, 0);
    {
        dim3 grid(PN / 64, PB);
        transpose_feat<<<grid, 256, 0, sT>>>(features);
    }
    cudaEventRecord(evT, sT);

    // Grid build: single direct-scatter pass
    scatter_direct<<<PB * PN / 256, 256>>>(xyz);

    // Ball query
    ball_query_grid<<<PB * PS / 8, 256>>>(new_xyz, fps_idx);

    // Join, then gather + write (+ counter reset tail)
    cudaStreamWaitEvent(0, evT, 0);
    gather_write<<<PB * (JTOT / TJ), 256>>>(xyz, new_xyz, out);
}